// round 6
// baseline (speedup 1.0000x reference)
#include <cuda_runtime.h>
#include <math.h>
#include <stdint.h>

#define NN      100000
#define NE      2000000
#define HH      64
#define TPB     256
#define NTILES_MAX ((NE/128) + 2)

typedef unsigned long long ull;

// ---------------- device scratch ----------------
__device__ __align__(16) float g_h[NN * HH];
__device__ __align__(16) float g_agg[NN * HH];   // invariant: zero on entry to each edge phase
__device__ int g_src[NE + 256];
__device__ int g_dst[NE + 256];
__device__ int g_cnt1;
__device__ int g_blkdone;
__device__ int g_cur0, g_cur1;
__device__ int g_b0p, g_ntiles;

__device__ __forceinline__ float sigf(float v) { return 1.f / (1.f + __expf(-v)); }

__device__ __forceinline__ void red_add_v4(float* p, float a, float b, float c, float d) {
    asm volatile("red.global.add.v4.f32 [%0], {%1, %2, %3, %4};"
                 :: "l"(p), "f"(a), "f"(b), "f"(c), "f"(d) : "memory");
}

// packed fp32x2 helpers
__device__ __forceinline__ ull pack2(float f) {
    ull r; unsigned u = __float_as_uint(f);
    asm("mov.b64 %0, {%1, %1};" : "=l"(r) : "r"(u));
    return r;
}
__device__ __forceinline__ void fma2(ull& d, ull a, ull b) {
    asm("fma.rn.f32x2 %0, %1, %2, %0;" : "+l"(d) : "l"(a), "l"(b));
}
__device__ __forceinline__ float2 unpack2(ull v) {
    unsigned lo, hi;
    asm("mov.b64 {%0, %1}, %2;" : "=r"(lo), "=r"(hi) : "l"(v));
    float2 r; r.x = __uint_as_float(lo); r.y = __uint_as_float(hi);
    return r;
}

// ---------------- fused edge count + scan (last-block pattern) ----------------
__global__ __launch_bounds__(TPB) void tg_countscan(const int* __restrict__ et) {
    __shared__ int sm[8];
    int tid = threadIdx.x;
    int s = 0;
    for (int e = blockIdx.x*TPB + tid; e < NE; e += gridDim.x*TPB) s += et[e];
    #pragma unroll
    for (int o = 16; o; o >>= 1) s += __shfl_xor_sync(0xffffffffu, s, o);
    if ((tid & 31) == 0) sm[tid >> 5] = s;
    __syncthreads();
    if (tid == 0) {
        int t = 0; for (int j = 0; j < 8; j++) t += sm[j];
        atomicAdd(&g_cnt1, t);
        __threadfence();
        int done = atomicAdd(&g_blkdone, 1);
        if (done == (int)gridDim.x - 1) {
            int c1 = atomicAdd(&g_cnt1, 0);
            g_cnt1 = 0; g_blkdone = 0;
            int c0 = NE - c1;
            int b0p = (c0 + 127) & ~127;
            int end1 = b0p + c1;
            int nt = (end1 + 127) >> 7;
            g_b0p = b0p; g_ntiles = nt;
            g_cur0 = 0; g_cur1 = b0p;
            for (int i = c0; i < b0p; i++)      { g_src[i] = 0; g_dst[i] = NN; }
            for (int i = end1; i < nt*128; i++) { g_src[i] = 0; g_dst[i] = NN; }
        }
    }
}

__global__ __launch_bounds__(TPB) void tg_scatter(const int* __restrict__ et,
                                                  const int* __restrict__ ei) {
    int lane = threadIdx.x & 31;
    unsigned lt = (1u << lane) - 1u;
    for (int e = blockIdx.x*TPB + threadIdx.x; e < NE; e += gridDim.x*TPB) {
        int t = et[e];
        unsigned m1 = __ballot_sync(0xffffffffu, t);
        int n1 = __popc(m1);
        int b0 = 0, b1 = 0;
        if (lane == 0) {
            b0 = atomicAdd(&g_cur0, 32 - n1);
            b1 = atomicAdd(&g_cur1, n1);
        }
        b0 = __shfl_sync(0xffffffffu, b0, 0);
        b1 = __shfl_sync(0xffffffffu, b1, 0);
        int pos = t ? (b1 + __popc(m1 & lt)) : (b0 + __popc(~m1 & lt));
        g_src[pos] = ei[e];
        g_dst[pos] = ei[NE + e];
    }
}

// ---------------- input projection: h = relu(LN(x@W+b)) ----------------
__global__ __launch_bounds__(TPB) void tg_input(const float* __restrict__ x,
    const float* __restrict__ in_w, const float* __restrict__ in_b,
    const float* __restrict__ ln_g, const float* __restrict__ ln_b)
{
    __shared__ float sw[256], sb[64], sg[64], sbn[64];
    int tid = threadIdx.x;
    if (tid < 256) sw[tid] = in_w[tid];
    if (tid < 64) { sb[tid] = in_b[tid]; sg[tid] = ln_g[tid]; sbn[tid] = ln_b[tid]; }
    __syncthreads();
    int lane = tid & 31;
    int warpsTotal = gridDim.x * (TPB / 32);
    for (int node = blockIdx.x * (TPB/32) + (tid >> 5); node < NN; node += warpsTotal) {
        float4 xv = *(const float4*)(x + node * 4);
        int c0 = lane * 2;
        float v0 = sb[c0]   + xv.x*sw[c0]   + xv.y*sw[64+c0]   + xv.z*sw[128+c0]   + xv.w*sw[192+c0];
        float v1 = sb[c0+1] + xv.x*sw[c0+1] + xv.y*sw[64+c0+1] + xv.z*sw[128+c0+1] + xv.w*sw[192+c0+1];
        float s = v0 + v1;
        #pragma unroll
        for (int o = 16; o; o >>= 1) s += __shfl_xor_sync(0xffffffffu, s, o);
        float mu = s * (1.0f/64.0f);
        float d0 = v0 - mu, d1 = v1 - mu;
        float q = d0*d0 + d1*d1;
        #pragma unroll
        for (int o = 16; o; o >>= 1) q += __shfl_xor_sync(0xffffffffu, q, o);
        float inv = rsqrtf(q * (1.0f/64.0f) + 1e-5f);
        g_h[node*64 + c0]   = fmaxf(d0*inv*sg[c0]   + sbn[c0],   0.f);
        g_h[node*64 + c0+1] = fmaxf(d1*inv*sg[c0+1] + sbn[c0+1], 0.f);
    }
}

// ---------------- edge MLP + scatter-add, dup-packed weights, no pack MOVs ----------------
// byte layout: smiT f32[128][128] @0 (64K) | sW1d ull[128][64] @65536 (64K)
//              sh1T f32[64][132] @131072 (33792) | sW2d ull[64][64] @164864 (32K)
//              sb1 @197632 | sb2 @197888 | end 198144
#define OFF_W1D  65536
#define OFF_H1T  131072
#define OFF_W2D  164864
#define OFF_B1   197632
#define OFF_B2   197888
#define EDGE_SMEM 198144
#define PE 132

__global__ __launch_bounds__(TPB, 1) void tg_edge(const float* __restrict__ w1g,
    const float* __restrict__ b1g, const float* __restrict__ w2g, const float* __restrict__ b2g)
{
    int tile = blockIdx.x;
    if (tile >= g_ntiles) return;
    int t = (tile * 128 >= g_b0p) ? 1 : 0;

    extern __shared__ char smraw[];
    float* smiT = (float*)smraw;
    ull*   sW1d = (ull*)(smraw + OFF_W1D);
    float* sh1T = (float*)(smraw + OFF_H1T);
    ull*   sW2d = (ull*)(smraw + OFF_W2D);
    float* sb1  = (float*)(smraw + OFF_B1);
    float* sb2  = (float*)(smraw + OFF_B2);

    int tid = threadIdx.x;
    const float* w1 = w1g + t * 8192;
    const float* w2 = w2g + t * 4096;
    for (int i = tid; i < 8192; i += TPB) sW1d[i] = pack2(w1[i]);
    for (int i = tid; i < 4096; i += TPB) sW2d[i] = pack2(w2[i]);
    if (tid < 64) { sb1[tid] = b1g[t*64 + tid]; sb2[tid] = b2g[t*64 + tid]; }

    // gather: mi = [h[src] | h[dst]] transposed -> smiT[k][e]
    int base = tile * 128;
    for (int i = tid; i < 4096; i += TPB) {
        int e = i & 127, kc = i >> 7;               // kc 0..31
        int idx = (kc < 16) ? g_src[base + e] : g_dst[base + e];
        if (idx >= NN) idx = 0;
        float4 v = ((const float4*)(g_h + (size_t)idx*64))[kc & 15];
        float* p = smiT + (kc*4)*128 + e;
        p[0] = v.x; p[128] = v.y; p[256] = v.z; p[384] = v.w;
    }
    __syncthreads();

    int eg = tid >> 4, cg = tid & 15;               // 16 edge groups x 16 col groups
    int e0 = eg * 8, c0 = cg * 4;

    // ---- stage 1: acc[p][j] = pair over edges (e0+2p, e0+2p+1), col c0+j ----
    ull acc[4][4];
    #pragma unroll
    for (int p = 0; p < 4; p++)
        #pragma unroll
        for (int j = 0; j < 4; j++) acc[p][j] = 0ull;

    const float* miB = smiT + e0;
    const ull*   wB  = sW1d + c0;
    #pragma unroll 4
    for (int k = 0; k < 128; k++) {
        ulonglong2 ma = *(const ulonglong2*)(miB + k*128);
        ulonglong2 mb = *(const ulonglong2*)(miB + k*128 + 4);
        ulonglong2 wa = *(const ulonglong2*)(wB + k*64);
        ulonglong2 wb = *(const ulonglong2*)(wB + k*64 + 2);
        fma2(acc[0][0], ma.x, wa.x); fma2(acc[0][1], ma.x, wa.y); fma2(acc[0][2], ma.x, wb.x); fma2(acc[0][3], ma.x, wb.y);
        fma2(acc[1][0], ma.y, wa.x); fma2(acc[1][1], ma.y, wa.y); fma2(acc[1][2], ma.y, wb.x); fma2(acc[1][3], ma.y, wb.y);
        fma2(acc[2][0], mb.x, wa.x); fma2(acc[2][1], mb.x, wa.y); fma2(acc[2][2], mb.x, wb.x); fma2(acc[2][3], mb.x, wb.y);
        fma2(acc[3][0], mb.y, wa.x); fma2(acc[3][1], mb.y, wa.y); fma2(acc[3][2], mb.y, wb.x); fma2(acc[3][3], mb.y, wb.y);
    }
    // relu+bias -> sh1T[c][e] (transposed, edge pairs contiguous)
    #pragma unroll
    for (int j = 0; j < 4; j++) {
        float b = sb1[c0 + j];
        #pragma unroll
        for (int p = 0; p < 4; p++) {
            float2 r = unpack2(acc[p][j]);
            float2 v; v.x = fmaxf(r.x + b, 0.f); v.y = fmaxf(r.y + b, 0.f);
            *(float2*)(sh1T + (c0 + j)*PE + e0 + 2*p) = v;
        }
    }
    __syncthreads();

    // ---- stage 2: same accumulator layout, contract over h1 cols (rows of sh1T) ----
    #pragma unroll
    for (int p = 0; p < 4; p++)
        #pragma unroll
        for (int j = 0; j < 4; j++) acc[p][j] = 0ull;

    const float* h1B = sh1T + e0;
    const ull*   w2B = sW2d + c0;
    #pragma unroll 4
    for (int k = 0; k < 64; k++) {
        ulonglong2 ma = *(const ulonglong2*)(h1B + k*PE);
        ulonglong2 mb = *(const ulonglong2*)(h1B + k*PE + 4);
        ulonglong2 wa = *(const ulonglong2*)(w2B + k*64);
        ulonglong2 wb = *(const ulonglong2*)(w2B + k*64 + 2);
        fma2(acc[0][0], ma.x, wa.x); fma2(acc[0][1], ma.x, wa.y); fma2(acc[0][2], ma.x, wb.x); fma2(acc[0][3], ma.x, wb.y);
        fma2(acc[1][0], ma.y, wa.x); fma2(acc[1][1], ma.y, wa.y); fma2(acc[1][2], ma.y, wb.x); fma2(acc[1][3], ma.y, wb.y);
        fma2(acc[2][0], mb.x, wa.x); fma2(acc[2][1], mb.x, wa.y); fma2(acc[2][2], mb.x, wb.x); fma2(acc[2][3], mb.x, wb.y);
        fma2(acc[3][0], mb.y, wa.x); fma2(acc[3][1], mb.y, wa.y); fma2(acc[3][2], mb.y, wb.x); fma2(acc[3][3], mb.y, wb.y);
    }
    float bb0 = sb2[c0], bb1 = sb2[c0+1], bb2v = sb2[c0+2], bb3 = sb2[c0+3];
    #pragma unroll
    for (int p = 0; p < 4; p++) {
        float2 r0 = unpack2(acc[p][0]);
        float2 r1 = unpack2(acc[p][1]);
        float2 r2 = unpack2(acc[p][2]);
        float2 r3 = unpack2(acc[p][3]);
        int dA = g_dst[base + e0 + 2*p];
        int dB = g_dst[base + e0 + 2*p + 1];
        if (dA < NN)
            red_add_v4(g_agg + (size_t)dA*64 + c0, r0.x+bb0, r1.x+bb1, r2.x+bb2v, r3.x+bb3);
        if (dB < NN)
            red_add_v4(g_agg + (size_t)dB*64 + c0, r0.y+bb0, r1.y+bb1, r2.y+bb2v, r3.y+bb3);
    }
}

// ---------------- GRU update (per layer), FFMA2 packed; zeroes g_agg ----------------
#define GRU_SMEM ((12288 + 12288) * 4)
__global__ __launch_bounds__(TPB) void tg_gru(const float* __restrict__ wi,
    const float* __restrict__ wh, const float* __restrict__ bi, const float* __restrict__ bh)
{
    extern __shared__ float sg[];
    float* sWi = sg; float* sWh = sg + 12288;
    for (int i = threadIdx.x; i < 3072; i += TPB) {
        ((float4*)sWi)[i] = ((const float4*)wi)[i];
        ((float4*)sWh)[i] = ((const float4*)wh)[i];
    }
    __syncthreads();
    int lane = threadIdx.x & 31;
    int warpsTotal = gridDim.x * (TPB/32);
    for (int node = blockIdx.x*(TPB/32) + (threadIdx.x>>5); node < NN; node += warpsTotal) {
        float* aggp = g_agg + (size_t)node*64;
        float* hp   = g_h   + (size_t)node*64;
        float a0 = aggp[lane], a1 = aggp[lane+32];
        float h0 = hp[lane],   h1 = hp[lane+32];
        aggp[lane] = 0.f; aggp[lane+32] = 0.f;
        float2 hpair = *(const float2*)(hp + 2*lane);
        ull gi[3] = {0,0,0}, gh[3] = {0,0,0};
        #pragma unroll
        for (int k = 0; k < 32; k++) {
            ull pa = pack2(__shfl_sync(0xffffffffu, a0, k));
            ull ph = pack2(__shfl_sync(0xffffffffu, h0, k));
            const float* pi = sWi + k*192 + 2*lane;
            const float* pw = sWh + k*192 + 2*lane;
            #pragma unroll
            for (int g = 0; g < 3; g++) {
                fma2(gi[g], pa, *(const ull*)(pi + 64*g));
                fma2(gh[g], ph, *(const ull*)(pw + 64*g));
            }
        }
        #pragma unroll
        for (int k = 0; k < 32; k++) {
            ull pa = pack2(__shfl_sync(0xffffffffu, a1, k));
            ull ph = pack2(__shfl_sync(0xffffffffu, h1, k));
            const float* pi = sWi + (k+32)*192 + 2*lane;
            const float* pw = sWh + (k+32)*192 + 2*lane;
            #pragma unroll
            for (int g = 0; g < 3; g++) {
                fma2(gi[g], pa, *(const ull*)(pi + 64*g));
                fma2(gh[g], ph, *(const ull*)(pw + 64*g));
            }
        }
        float2 vir = unpack2(gi[0]), vhr = unpack2(gh[0]);
        float2 viz = unpack2(gi[1]), vhz = unpack2(gh[1]);
        float2 vin = unpack2(gi[2]), vhn = unpack2(gh[2]);
        float2 bir = *(const float2*)(bi + 2*lane),        bhr = *(const float2*)(bh + 2*lane);
        float2 biz = *(const float2*)(bi + 64 + 2*lane),   bhz = *(const float2*)(bh + 64 + 2*lane);
        float2 bin = *(const float2*)(bi + 128 + 2*lane),  bhn = *(const float2*)(bh + 128 + 2*lane);
        float r0 = sigf(vir.x + vhr.x + bir.x + bhr.x);
        float r1 = sigf(vir.y + vhr.y + bir.y + bhr.y);
        float z0 = sigf(viz.x + vhz.x + biz.x + bhz.x);
        float z1 = sigf(viz.y + vhz.y + biz.y + bhz.y);
        float n0 = tanhf(vin.x + bin.x + r0*(vhn.x + bhn.x));
        float n1 = tanhf(vin.y + bin.y + r1*(vhn.y + bhn.y));
        float2 outp;
        outp.x = (1.f - z0)*n0 + z0*hpair.x;
        outp.y = (1.f - z1)*n1 + z1*hpair.y;
        *(float2*)(hp + 2*lane) = outp;
    }
}

// ---------------- readout + correction ----------------
__global__ __launch_bounds__(TPB) void tg_readout(const float* __restrict__ x,
    const int* __restrict__ ntype, const float* __restrict__ w1, const float* __restrict__ b1,
    const float* __restrict__ w2, const float* __restrict__ b2, float* __restrict__ out)
{
    __shared__ float sw[4096], sv[64], sb[64];
    for (int i = threadIdx.x; i < 4096; i += TPB) sw[i] = w1[i];
    if (threadIdx.x < 64) { sv[threadIdx.x] = w2[threadIdx.x]; sb[threadIdx.x] = b1[threadIdx.x]; }
    __syncthreads();
    int lane = threadIdx.x & 31;
    int warpsTotal = gridDim.x * (TPB/32);
    for (int node = blockIdx.x*(TPB/32) + (threadIdx.x>>5); node < NN; node += warpsTotal) {
        const float* hp = g_h + (size_t)node*64;
        float h0 = hp[lane], h1 = hp[lane+32];
        float acc0 = 0.f, acc1 = 0.f;
        #pragma unroll
        for (int k = 0; k < 32; k++) {
            float hk = __shfl_sync(0xffffffffu, h0, k);
            acc0 = fmaf(hk, sw[k*64+lane],    acc0);
            acc1 = fmaf(hk, sw[k*64+lane+32], acc1);
        }
        #pragma unroll
        for (int k = 0; k < 32; k++) {
            float hk = __shfl_sync(0xffffffffu, h1, k);
            acc0 = fmaf(hk, sw[(k+32)*64+lane],    acc0);
            acc1 = fmaf(hk, sw[(k+32)*64+lane+32], acc1);
        }
        float t0 = fmaxf(acc0 + sb[lane],    0.f);
        float t1 = fmaxf(acc1 + sb[lane+32], 0.f);
        float p = t0*sv[lane] + t1*sv[lane+32];
        #pragma unroll
        for (int o = 16; o; o >>= 1) p += __shfl_xor_sync(0xffffffffu, p, o);
        if (lane == 0)
            out[node] = (ntype[node] == 0) ? (x[node*4] + p + b2[0]) : 0.f;
    }
}

// ---------------- launch ----------------
extern "C" void kernel_launch(void* const* d_in, const int* in_sizes, int n_in,
                              void* d_out, int out_size)
{
    const float* x        = (const float*)d_in[0];
    const int*   ntype    = (const int*)  d_in[1];
    const int*   eindex   = (const int*)  d_in[2];
    const int*   etype    = (const int*)  d_in[3];
    const float* in_w     = (const float*)d_in[4];
    const float* in_b     = (const float*)d_in[5];
    const float* ln_g     = (const float*)d_in[6];
    const float* ln_b     = (const float*)d_in[7];
    const float* mlp_w1   = (const float*)d_in[8];
    const float* mlp_b1   = (const float*)d_in[9];
    const float* mlp_w2   = (const float*)d_in[10];
    const float* mlp_b2   = (const float*)d_in[11];
    const float* gru_wi   = (const float*)d_in[12];
    const float* gru_wh   = (const float*)d_in[13];
    const float* gru_bi   = (const float*)d_in[14];
    const float* gru_bh   = (const float*)d_in[15];
    const float* ro_w1    = (const float*)d_in[16];
    const float* ro_b1    = (const float*)d_in[17];
    const float* ro_w2    = (const float*)d_in[18];
    const float* ro_b2    = (const float*)d_in[19];
    float* out = (float*)d_out;

    cudaFuncSetAttribute(tg_edge, cudaFuncAttributeMaxDynamicSharedMemorySize, EDGE_SMEM);
    cudaFuncSetAttribute(tg_gru,  cudaFuncAttributeMaxDynamicSharedMemorySize, GRU_SMEM);

    // order chosen so tg_edge (layer 0) is the 4th launch — the slot ncu profiles
    tg_countscan<<<512, TPB>>>(etype);
    tg_scatter<<<512, TPB>>>(etype, eindex);
    tg_input<<<304, TPB>>>(x, in_w, in_b, ln_g, ln_b);

    for (int l = 0; l < 3; l++) {
        tg_edge<<<NTILES_MAX, TPB, EDGE_SMEM>>>(mlp_w1 + l*2*8192, mlp_b1 + l*2*64,
                                                mlp_w2 + l*2*4096, mlp_b2 + l*2*64);
        tg_gru<<<296, TPB, GRU_SMEM>>>(gru_wi + l*12288, gru_wh + l*12288,
                                       gru_bi + l*192,   gru_bh + l*192);
    }
    tg_readout<<<304, TPB>>>(x, ntype, ro_w1, ro_b1, ro_w2, ro_b2, out);
}

// round 8
// speedup vs baseline: 1.8935x; 1.8935x over previous
#include <cuda_runtime.h>
#include <math.h>
#include <stdint.h>

#define NN      100000
#define NE      2000000
#define HH      64
#define TPB     256
#define ETPB    512
#define NTILES_MAX ((NE/128) + 2)

typedef unsigned long long ull;

// ---------------- device scratch ----------------
__device__ __align__(16) float g_h[NN * HH];
__device__ __align__(16) float g_agg[NN * HH];   // invariant: zero on entry to each edge phase
__device__ int g_src[NE + 256];
__device__ int g_dst[NE + 256];
__device__ int g_cnt1;
__device__ int g_blkdone;
__device__ int g_cur0, g_cur1;
__device__ int g_b0p, g_ntiles;

__device__ __forceinline__ float sigf(float v) { return 1.f / (1.f + __expf(-v)); }

__device__ __forceinline__ void red_add_v4(float* p, float a, float b, float c, float d) {
    asm volatile("red.global.add.v4.f32 [%0], {%1, %2, %3, %4};"
                 :: "l"(p), "f"(a), "f"(b), "f"(c), "f"(d) : "memory");
}

// packed fp32x2 helpers
__device__ __forceinline__ ull pack2(float f) {
    ull r; unsigned u = __float_as_uint(f);
    asm("mov.b64 %0, {%1, %1};" : "=l"(r) : "r"(u));
    return r;
}
__device__ __forceinline__ void fma2(ull& d, ull a, ull b) {
    asm("fma.rn.f32x2 %0, %1, %2, %0;" : "+l"(d) : "l"(a), "l"(b));
}
__device__ __forceinline__ float2 unpack2(ull v) {
    unsigned lo, hi;
    asm("mov.b64 {%0, %1}, %2;" : "=r"(lo), "=r"(hi) : "l"(v));
    float2 r; r.x = __uint_as_float(lo); r.y = __uint_as_float(hi);
    return r;
}

// ---------------- fused edge count + scan (last-block pattern) ----------------
__global__ __launch_bounds__(TPB) void tg_countscan(const int* __restrict__ et) {
    __shared__ int sm[8];
    int tid = threadIdx.x;
    int s = 0;
    for (int e = blockIdx.x*TPB + tid; e < NE; e += gridDim.x*TPB) s += et[e];
    #pragma unroll
    for (int o = 16; o; o >>= 1) s += __shfl_xor_sync(0xffffffffu, s, o);
    if ((tid & 31) == 0) sm[tid >> 5] = s;
    __syncthreads();
    if (tid == 0) {
        int t = 0; for (int j = 0; j < 8; j++) t += sm[j];
        atomicAdd(&g_cnt1, t);
        __threadfence();
        int done = atomicAdd(&g_blkdone, 1);
        if (done == (int)gridDim.x - 1) {
            int c1 = atomicAdd(&g_cnt1, 0);
            g_cnt1 = 0; g_blkdone = 0;
            int c0 = NE - c1;
            int b0p = (c0 + 127) & ~127;
            int end1 = b0p + c1;
            int nt = (end1 + 127) >> 7;
            g_b0p = b0p; g_ntiles = nt;
            g_cur0 = 0; g_cur1 = b0p;
            for (int i = c0; i < b0p; i++)      { g_src[i] = 0; g_dst[i] = NN; }
            for (int i = end1; i < nt*128; i++) { g_src[i] = 0; g_dst[i] = NN; }
        }
    }
}

__global__ __launch_bounds__(TPB) void tg_scatter(const int* __restrict__ et,
                                                  const int* __restrict__ ei) {
    int lane = threadIdx.x & 31;
    unsigned lt = (1u << lane) - 1u;
    for (int e = blockIdx.x*TPB + threadIdx.x; e < NE; e += gridDim.x*TPB) {
        int t = et[e];
        unsigned m1 = __ballot_sync(0xffffffffu, t);
        int n1 = __popc(m1);
        int b0 = 0, b1 = 0;
        if (lane == 0) {
            b0 = atomicAdd(&g_cur0, 32 - n1);
            b1 = atomicAdd(&g_cur1, n1);
        }
        b0 = __shfl_sync(0xffffffffu, b0, 0);
        b1 = __shfl_sync(0xffffffffu, b1, 0);
        int pos = t ? (b1 + __popc(m1 & lt)) : (b0 + __popc(~m1 & lt));
        g_src[pos] = ei[e];
        g_dst[pos] = ei[NE + e];
    }
}

// ---------------- input projection: h = relu(LN(x@W+b)) ----------------
__global__ __launch_bounds__(TPB) void tg_input(const float* __restrict__ x,
    const float* __restrict__ in_w, const float* __restrict__ in_b,
    const float* __restrict__ ln_g, const float* __restrict__ ln_b)
{
    __shared__ float sw[256], sb[64], sg[64], sbn[64];
    int tid = threadIdx.x;
    if (tid < 256) sw[tid] = in_w[tid];
    if (tid < 64) { sb[tid] = in_b[tid]; sg[tid] = ln_g[tid]; sbn[tid] = ln_b[tid]; }
    __syncthreads();
    int lane = tid & 31;
    int warpsTotal = gridDim.x * (TPB / 32);
    for (int node = blockIdx.x * (TPB/32) + (tid >> 5); node < NN; node += warpsTotal) {
        float4 xv = *(const float4*)(x + node * 4);
        int c0 = lane * 2;
        float v0 = sb[c0]   + xv.x*sw[c0]   + xv.y*sw[64+c0]   + xv.z*sw[128+c0]   + xv.w*sw[192+c0];
        float v1 = sb[c0+1] + xv.x*sw[c0+1] + xv.y*sw[64+c0+1] + xv.z*sw[128+c0+1] + xv.w*sw[192+c0+1];
        float s = v0 + v1;
        #pragma unroll
        for (int o = 16; o; o >>= 1) s += __shfl_xor_sync(0xffffffffu, s, o);
        float mu = s * (1.0f/64.0f);
        float d0 = v0 - mu, d1 = v1 - mu;
        float q = d0*d0 + d1*d1;
        #pragma unroll
        for (int o = 16; o; o >>= 1) q += __shfl_xor_sync(0xffffffffu, q, o);
        float inv = rsqrtf(q * (1.0f/64.0f) + 1e-5f);
        g_h[node*64 + c0]   = fmaxf(d0*inv*sg[c0]   + sbn[c0],   0.f);
        g_h[node*64 + c0+1] = fmaxf(d1*inv*sg[c0+1] + sbn[c0+1], 0.f);
    }
}

// ---------------- persistent edge MLP + scatter-add ----------------
// smem floats: smi[128][128] | sh1[128][68] | sW1[2][128][64] | sW2[2][64][64]
//              sb1[2][64] | sb2[2][64]
#define PH1 68
#define OFF_H1  16384
#define OFF_W1  (OFF_H1 + 128*PH1)
#define OFF_W2  (OFF_W1 + 16384)
#define OFF_B1  (OFF_W2 + 8192)
#define OFF_B2  (OFF_B1 + 128)
#define EDGE_SMEM ((OFF_B2 + 128) * 4)

__global__ __launch_bounds__(ETPB, 1) void tg_edge(const float* __restrict__ w1g,
    const float* __restrict__ b1g, const float* __restrict__ w2g, const float* __restrict__ b2g)
{
    extern __shared__ float sm[];
    float* smi = sm;               // [128][128]
    float* sh1 = sm + OFF_H1;      // [128][PH1]
    float* sW1 = sm + OFF_W1;      // [2][128][64]
    float* sW2 = sm + OFF_W2;      // [2][64][64]
    float* sb1 = sm + OFF_B1;      // [2][64]
    float* sb2 = sm + OFF_B2;      // [2][64]

    int tid = threadIdx.x;
    // load BOTH edge types' weights once (persistent block)
    for (int i = tid; i < 4096; i += ETPB) ((float4*)sW1)[i] = ((const float4*)w1g)[i];
    for (int i = tid; i < 2048; i += ETPB) ((float4*)sW2)[i] = ((const float4*)w2g)[i];
    if (tid < 128) { sb1[tid] = b1g[tid]; sb2[tid] = b2g[tid]; }

    int eg = tid >> 4, cg = tid & 15;           // 32 edge groups x 16 col groups
    int e0 = eg * 4, c0 = cg * 4;
    int ntiles = g_ntiles, b0p = g_b0p;

    for (int tile = blockIdx.x; tile < ntiles; tile += gridDim.x) {
        int base = tile * 128;
        int t = (base >= b0p) ? 1 : 0;
        const float* W1t = sW1 + t * 8192;
        const float* W2t = sW2 + t * 4096;

        __syncthreads();  // previous tile fully consumed before overwriting smi
        // gather mi row-major: warp = 1 edge, 32 lanes = 32 float4 (src|dst)
        for (int i = tid; i < 4096; i += ETPB) {
            int e = i >> 5, c = i & 31;
            int idx = (c < 16) ? g_src[base + e] : g_dst[base + e];
            if (idx >= NN) idx = 0;
            ((float4*)smi)[e*32 + c] = ((const float4*)(g_h + (size_t)idx*64))[c & 15];
        }
        __syncthreads();

        // ---- stage 1: out[e][c] = sum_k mi[e][k] * W1[k][c] ----
        ull acc[4][2];
        #pragma unroll
        for (int e = 0; e < 4; e++) { acc[e][0] = 0ull; acc[e][1] = 0ull; }
        const float* miB = smi + e0*128;
        const float* wB  = W1t + c0;
        #pragma unroll 4
        for (int k = 0; k < 128; k++) {
            ulonglong2 wv = *(const ulonglong2*)(wB + k*64);
            ull m0 = pack2(miB[k]);
            ull m1 = pack2(miB[128 + k]);
            ull m2 = pack2(miB[256 + k]);
            ull m3 = pack2(miB[384 + k]);
            fma2(acc[0][0], m0, wv.x); fma2(acc[0][1], m0, wv.y);
            fma2(acc[1][0], m1, wv.x); fma2(acc[1][1], m1, wv.y);
            fma2(acc[2][0], m2, wv.x); fma2(acc[2][1], m2, wv.y);
            fma2(acc[3][0], m3, wv.x); fma2(acc[3][1], m3, wv.y);
        }
        {
            float b0f = sb1[t*64 + c0], b1f = sb1[t*64 + c0+1];
            float b2f = sb1[t*64 + c0+2], b3f = sb1[t*64 + c0+3];
            #pragma unroll
            for (int e = 0; e < 4; e++) {
                float2 lo = unpack2(acc[e][0]);
                float2 hi = unpack2(acc[e][1]);
                float4 v;
                v.x = fmaxf(lo.x + b0f, 0.f); v.y = fmaxf(lo.y + b1f, 0.f);
                v.z = fmaxf(hi.x + b2f, 0.f); v.w = fmaxf(hi.y + b3f, 0.f);
                *(float4*)(sh1 + (e0 + e)*PH1 + c0) = v;
            }
        }
        __syncthreads();

        // ---- stage 2: msg[e][c] = sum_k h1[e][k] * W2[k][c] ----
        #pragma unroll
        for (int e = 0; e < 4; e++) { acc[e][0] = 0ull; acc[e][1] = 0ull; }
        const float* h1B = sh1 + e0*PH1;
        const float* w2B = W2t + c0;
        #pragma unroll 4
        for (int k = 0; k < 64; k++) {
            ulonglong2 wv = *(const ulonglong2*)(w2B + k*64);
            ull m0 = pack2(h1B[k]);
            ull m1 = pack2(h1B[PH1 + k]);
            ull m2 = pack2(h1B[2*PH1 + k]);
            ull m3 = pack2(h1B[3*PH1 + k]);
            fma2(acc[0][0], m0, wv.x); fma2(acc[0][1], m0, wv.y);
            fma2(acc[1][0], m1, wv.x); fma2(acc[1][1], m1, wv.y);
            fma2(acc[2][0], m2, wv.x); fma2(acc[2][1], m2, wv.y);
            fma2(acc[3][0], m3, wv.x); fma2(acc[3][1], m3, wv.y);
        }
        {
            float b0f = sb2[t*64 + c0], b1f = sb2[t*64 + c0+1];
            float b2f = sb2[t*64 + c0+2], b3f = sb2[t*64 + c0+3];
            #pragma unroll
            for (int e = 0; e < 4; e++) {
                int dst = g_dst[base + e0 + e];
                if (dst < NN) {
                    float2 lo = unpack2(acc[e][0]);
                    float2 hi = unpack2(acc[e][1]);
                    red_add_v4(g_agg + (size_t)dst*64 + c0,
                               lo.x + b0f, lo.y + b1f, hi.x + b2f, hi.y + b3f);
                }
            }
        }
    }
}

// ---------------- GRU update (per layer), FFMA2 packed; zeroes g_agg ----------------
#define GRU_SMEM ((12288 + 12288) * 4)
__global__ __launch_bounds__(TPB) void tg_gru(const float* __restrict__ wi,
    const float* __restrict__ wh, const float* __restrict__ bi, const float* __restrict__ bh)
{
    extern __shared__ float sg[];
    float* sWi = sg; float* sWh = sg + 12288;
    for (int i = threadIdx.x; i < 3072; i += TPB) {
        ((float4*)sWi)[i] = ((const float4*)wi)[i];
        ((float4*)sWh)[i] = ((const float4*)wh)[i];
    }
    __syncthreads();
    int lane = threadIdx.x & 31;
    int warpsTotal = gridDim.x * (TPB/32);
    for (int node = blockIdx.x*(TPB/32) + (threadIdx.x>>5); node < NN; node += warpsTotal) {
        float* aggp = g_agg + (size_t)node*64;
        float* hp   = g_h   + (size_t)node*64;
        float a0 = aggp[lane], a1 = aggp[lane+32];
        float h0 = hp[lane],   h1 = hp[lane+32];
        aggp[lane] = 0.f; aggp[lane+32] = 0.f;
        float2 hpair = *(const float2*)(hp + 2*lane);
        ull gi[3] = {0,0,0}, gh[3] = {0,0,0};
        #pragma unroll
        for (int k = 0; k < 32; k++) {
            ull pa = pack2(__shfl_sync(0xffffffffu, a0, k));
            ull ph = pack2(__shfl_sync(0xffffffffu, h0, k));
            const float* pi = sWi + k*192 + 2*lane;
            const float* pw = sWh + k*192 + 2*lane;
            #pragma unroll
            for (int g = 0; g < 3; g++) {
                fma2(gi[g], pa, *(const ull*)(pi + 64*g));
                fma2(gh[g], ph, *(const ull*)(pw + 64*g));
            }
        }
        #pragma unroll
        for (int k = 0; k < 32; k++) {
            ull pa = pack2(__shfl_sync(0xffffffffu, a1, k));
            ull ph = pack2(__shfl_sync(0xffffffffu, h1, k));
            const float* pi = sWi + (k+32)*192 + 2*lane;
            const float* pw = sWh + (k+32)*192 + 2*lane;
            #pragma unroll
            for (int g = 0; g < 3; g++) {
                fma2(gi[g], pa, *(const ull*)(pi + 64*g));
                fma2(gh[g], ph, *(const ull*)(pw + 64*g));
            }
        }
        float2 vir = unpack2(gi[0]), vhr = unpack2(gh[0]);
        float2 viz = unpack2(gi[1]), vhz = unpack2(gh[1]);
        float2 vin = unpack2(gi[2]), vhn = unpack2(gh[2]);
        float2 bir = *(const float2*)(bi + 2*lane),        bhr = *(const float2*)(bh + 2*lane);
        float2 biz = *(const float2*)(bi + 64 + 2*lane),   bhz = *(const float2*)(bh + 64 + 2*lane);
        float2 bin = *(const float2*)(bi + 128 + 2*lane),  bhn = *(const float2*)(bh + 128 + 2*lane);
        float r0 = sigf(vir.x + vhr.x + bir.x + bhr.x);
        float r1 = sigf(vir.y + vhr.y + bir.y + bhr.y);
        float z0 = sigf(viz.x + vhz.x + biz.x + bhz.x);
        float z1 = sigf(viz.y + vhz.y + biz.y + bhz.y);
        float n0 = tanhf(vin.x + bin.x + r0*(vhn.x + bhn.x));
        float n1 = tanhf(vin.y + bin.y + r1*(vhn.y + bhn.y));
        float2 outp;
        outp.x = (1.f - z0)*n0 + z0*hpair.x;
        outp.y = (1.f - z1)*n1 + z1*hpair.y;
        *(float2*)(hp + 2*lane) = outp;
    }
}

// ---------------- readout + correction ----------------
__global__ __launch_bounds__(TPB) void tg_readout(const float* __restrict__ x,
    const int* __restrict__ ntype, const float* __restrict__ w1, const float* __restrict__ b1,
    const float* __restrict__ w2, const float* __restrict__ b2, float* __restrict__ out)
{
    __shared__ float sw[4096], sv[64], sb[64];
    for (int i = threadIdx.x; i < 4096; i += TPB) sw[i] = w1[i];
    if (threadIdx.x < 64) { sv[threadIdx.x] = w2[threadIdx.x]; sb[threadIdx.x] = b1[threadIdx.x]; }
    __syncthreads();
    int lane = threadIdx.x & 31;
    int warpsTotal = gridDim.x * (TPB/32);
    for (int node = blockIdx.x*(TPB/32) + (threadIdx.x>>5); node < NN; node += warpsTotal) {
        const float* hp = g_h + (size_t)node*64;
        float h0 = hp[lane], h1 = hp[lane+32];
        float acc0 = 0.f, acc1 = 0.f;
        #pragma unroll
        for (int k = 0; k < 32; k++) {
            float hk = __shfl_sync(0xffffffffu, h0, k);
            acc0 = fmaf(hk, sw[k*64+lane],    acc0);
            acc1 = fmaf(hk, sw[k*64+lane+32], acc1);
        }
        #pragma unroll
        for (int k = 0; k < 32; k++) {
            float hk = __shfl_sync(0xffffffffu, h1, k);
            acc0 = fmaf(hk, sw[(k+32)*64+lane],    acc0);
            acc1 = fmaf(hk, sw[(k+32)*64+lane+32], acc1);
        }
        float t0 = fmaxf(acc0 + sb[lane],    0.f);
        float t1 = fmaxf(acc1 + sb[lane+32], 0.f);
        float p = t0*sv[lane] + t1*sv[lane+32];
        #pragma unroll
        for (int o = 16; o; o >>= 1) p += __shfl_xor_sync(0xffffffffu, p, o);
        if (lane == 0)
            out[node] = (ntype[node] == 0) ? (x[node*4] + p + b2[0]) : 0.f;
    }
}

// ---------------- launch ----------------
extern "C" void kernel_launch(void* const* d_in, const int* in_sizes, int n_in,
                              void* d_out, int out_size)
{
    const float* x        = (const float*)d_in[0];
    const int*   ntype    = (const int*)  d_in[1];
    const int*   eindex   = (const int*)  d_in[2];
    const int*   etype    = (const int*)  d_in[3];
    const float* in_w     = (const float*)d_in[4];
    const float* in_b     = (const float*)d_in[5];
    const float* ln_g     = (const float*)d_in[6];
    const float* ln_b     = (const float*)d_in[7];
    const float* mlp_w1   = (const float*)d_in[8];
    const float* mlp_b1   = (const float*)d_in[9];
    const float* mlp_w2   = (const float*)d_in[10];
    const float* mlp_b2   = (const float*)d_in[11];
    const float* gru_wi   = (const float*)d_in[12];
    const float* gru_wh   = (const float*)d_in[13];
    const float* gru_bi   = (const float*)d_in[14];
    const float* gru_bh   = (const float*)d_in[15];
    const float* ro_w1    = (const float*)d_in[16];
    const float* ro_b1    = (const float*)d_in[17];
    const float* ro_w2    = (const float*)d_in[18];
    const float* ro_b2    = (const float*)d_in[19];
    float* out = (float*)d_out;

    cudaFuncSetAttribute(tg_edge, cudaFuncAttributeMaxDynamicSharedMemorySize, EDGE_SMEM);
    cudaFuncSetAttribute(tg_gru,  cudaFuncAttributeMaxDynamicSharedMemorySize, GRU_SMEM);

    // order chosen so tg_edge (layer 0) is the 4th launch — the slot ncu profiles
    tg_countscan<<<512, TPB>>>(etype);
    tg_scatter<<<512, TPB>>>(etype, eindex);
    tg_input<<<304, TPB>>>(x, in_w, in_b, ln_g, ln_b);

    for (int l = 0; l < 3; l++) {
        tg_edge<<<148, ETPB, EDGE_SMEM>>>(mlp_w1 + l*2*8192, mlp_b1 + l*2*64,
                                          mlp_w2 + l*2*4096, mlp_b2 + l*2*64);
        tg_gru<<<296, TPB, GRU_SMEM>>>(gru_wi + l*12288, gru_wh + l*12288,
                                       gru_bi + l*192,   gru_bh + l*192);
    }
    tg_readout<<<304, TPB>>>(x, ntype, ro_w1, ro_b1, ro_w2, ro_b2, out);
}